// round 1
// baseline (speedup 1.0000x reference)
#include <cuda_runtime.h>
#include <math.h>

// ---- problem constants ----
#define Bsz 4096
#define Lm  30
#define Wm  5
#define Am  30
#define Em  128
#define Cch 40
#define Hm  128
#define Tm  3
#define LIN 200
#define FK  208          // padded K for GEMM
#define Nt  (Bsz*Lm)     // 122880 tokens
#define G4  512          // 4*H gates

// ---- device scratch (static, allowed) ----
__device__ float g_M[Am*Cch*3];        // folded emb*conv*bn
__device__ float g_bias1[Cch];
__device__ float g_wihP[2][G4*FK];     // padded input weights [dir][g][k]
__device__ float g_whhT[2][Hm*G4];     // transposed recurrent weights [dir][k][g]
__device__ float g_fcf[Tm*Hm];
__device__ float g_fcb[Tm*Hm];
__device__ float g_cbias[Tm];
__device__ float g_feat[(size_t)Nt*FK];        // ~102 MB
__device__ float g_gates[2][(size_t)Nt*G4];    // ~503 MB
__device__ float g_h[2][(size_t)Nt*Hm];        // ~126 MB
__device__ float g_emis[(size_t)Nt*Tm];

// ======================= prep kernels =======================
__global__ void prep_tables(const float* __restrict__ emb,
                            const float* __restrict__ conv_w,
                            const float* __restrict__ conv_b,
                            const float* __restrict__ g1,
                            const float* __restrict__ b1,
                            const float* __restrict__ m1,
                            const float* __restrict__ v1)
{
    int i = blockIdx.x*blockDim.x + threadIdx.x;
    if (i < Am*Cch*3) {
        int k = i % 3;
        int c = (i/3) % Cch;
        int a = i / (3*Cch);
        float s = 0.f;
        for (int e = 0; e < Em; e++)
            s += emb[a*Em + e] * conv_w[(c*Em + e)*3 + k];
        float sc = g1[c] * rsqrtf(v1[c] + 1e-5f);
        g_M[i] = s * sc;
    } else if (i < Am*Cch*3 + Cch) {
        int c = i - Am*Cch*3;
        float sc = g1[c] * rsqrtf(v1[c] + 1e-5f);
        g_bias1[c] = (conv_b[c] - m1[c]) * sc + b1[c];
    }
}

__global__ void prep_pack(const float* __restrict__ wihf, const float* __restrict__ whhf,
                          const float* __restrict__ wihb, const float* __restrict__ whhb)
{
    int stride = gridDim.x * blockDim.x;
    int t0 = blockIdx.x*blockDim.x + threadIdx.x;
    for (int i = t0; i < G4*FK; i += stride) {
        int g = i / FK, k = i % FK;
        float vf = (k < LIN) ? wihf[g*LIN + k] : 0.f;
        float vb = (k < LIN) ? wihb[g*LIN + k] : 0.f;
        g_wihP[0][i] = vf;
        g_wihP[1][i] = vb;
    }
    for (int i = t0; i < Hm*G4; i += stride) {
        int k = i / G4, g = i % G4;
        g_whhT[0][i] = whhf[g*Hm + k];
        g_whhT[1][i] = whhb[g*Hm + k];
    }
}

__global__ void prep_fc(const float* __restrict__ g2, const float* __restrict__ b2,
                        const float* __restrict__ m2, const float* __restrict__ v2,
                        const float* __restrict__ fcw, const float* __restrict__ fcbias)
{
    int t = threadIdx.x;
    if (t < Hm) {
        float s2a = g2[t]       * rsqrtf(v2[t]       + 1e-5f);
        float s2b = g2[Hm + t]  * rsqrtf(v2[Hm + t]  + 1e-5f);
        for (int tt = 0; tt < Tm; tt++) {
            g_fcf[tt*Hm + t] = fcw[tt*2*Hm + t]      * s2a;
            g_fcb[tt*Hm + t] = fcw[tt*2*Hm + Hm + t] * s2b;
        }
    }
    if (t < Tm) {
        float s = fcbias[t];
        for (int j = 0; j < 2*Hm; j++) {
            float s2 = g2[j] * rsqrtf(v2[j] + 1e-5f);
            s += (b2[j] - m2[j]*s2) * fcw[t*2*Hm + j];
        }
        g_cbias[t] = s;
    }
}

// ======================= featurize (conv+bn+relu+pool) =======================
__global__ void featurize(const int* __restrict__ x)
{
    int idx = blockIdx.x*blockDim.x + threadIdx.x;
    if (idx >= Nt*Cch) return;
    int n = idx / Cch, c = idx % Cch;
    int sym[Wm];
#pragma unroll
    for (int w = 0; w < Wm; w++) sym[w] = x[n*Wm + w];
    float y[Wm];
    float bb = g_bias1[c];
#pragma unroll
    for (int w = 0; w < Wm; w++) {
        float v = bb;
#pragma unroll
        for (int k = 0; k < 3; k++) {
            int p = w + k - 1;
            if (p >= 0 && p < Wm)
                v += g_M[sym[p]*(Cch*3) + c*3 + k];
        }
        y[w] = fmaxf(v, 0.f);
    }
    size_t base = (size_t)n*FK + c*Wm;
#pragma unroll
    for (int w = 0; w < Wm; w++) {
        float p = y[w];
        if (w > 0)      p = fmaxf(p, y[w-1]);
        if (w < Wm-1)   p = fmaxf(p, y[w+1]);
        g_feat[base + w] = p;
    }
    if (c < FK - LIN) g_feat[(size_t)n*FK + LIN + c] = 0.f; // zero pad columns
}

// ======================= input GEMM: gates = feat @ w_ih^T + b =======================
__global__ __launch_bounds__(256) void gemm_gates(int dir, const float* __restrict__ bias)
{
    const float* __restrict__ A  = g_feat;
    const float* __restrict__ Bt = g_wihP[dir];
    float* __restrict__ Co = g_gates[dir];

    __shared__ __align__(16) float As[16][64];
    __shared__ __align__(16) float Bs[16][64];

    int m0 = blockIdx.x*64, n0 = blockIdx.y*64;
    int t  = threadIdx.x;
    int lr = t >> 2;          // 0..63
    int lc = (t & 3) * 4;     // 0,4,8,12
    int tn = t & 15, tm = t >> 4;

    float acc[4][4];
#pragma unroll
    for (int i = 0; i < 4; i++)
#pragma unroll
        for (int j = 0; j < 4; j++) acc[i][j] = 0.f;

    for (int k0 = 0; k0 < FK; k0 += 16) {
        float4 av = *(const float4*)(A  + (size_t)(m0+lr)*FK + k0 + lc);
        float4 bv = *(const float4*)(Bt + (size_t)(n0+lr)*FK + k0 + lc);
        As[lc+0][lr]=av.x; As[lc+1][lr]=av.y; As[lc+2][lr]=av.z; As[lc+3][lr]=av.w;
        Bs[lc+0][lr]=bv.x; Bs[lc+1][lr]=bv.y; Bs[lc+2][lr]=bv.z; Bs[lc+3][lr]=bv.w;
        __syncthreads();
#pragma unroll
        for (int k = 0; k < 16; k++) {
            float4 a4 = *(const float4*)&As[k][tm*4];
            float4 b4 = *(const float4*)&Bs[k][tn*4];
            float avv[4] = {a4.x, a4.y, a4.z, a4.w};
            float bvv[4] = {b4.x, b4.y, b4.z, b4.w};
#pragma unroll
            for (int i = 0; i < 4; i++)
#pragma unroll
                for (int j = 0; j < 4; j++)
                    acc[i][j] += avv[i]*bvv[j];
        }
        __syncthreads();
    }
    int gcol = n0 + tn*4;
#pragma unroll
    for (int i = 0; i < 4; i++) {
        float4 o;
        o.x = acc[i][0] + bias[gcol+0];
        o.y = acc[i][1] + bias[gcol+1];
        o.z = acc[i][2] + bias[gcol+2];
        o.w = acc[i][3] + bias[gcol+3];
        *(float4*)(Co + (size_t)(m0 + tm*4 + i)*G4 + gcol) = o;
    }
}

// ======================= LSTM recurrence =======================
// One block = 32 batch rows. 256 threads: j = t&127 (H index), half = t>>7
// picks which 16 rows this thread owns. h kept in shared (k-major, double
// buffered), c in registers.
__global__ __launch_bounds__(256, 1) void lstm_kernel(int dir)
{
    const float* __restrict__ gates = g_gates[dir];
    const float* __restrict__ whhT  = g_whhT[dir];
    float* __restrict__ hout        = g_h[dir];

    __shared__ __align__(16) float hs[2][Hm][36];

    int t = threadIdx.x;
    int j = t & 127;
    int half = t >> 7;
    int r0 = blockIdx.x * 32;

    for (int i = t; i < 2*Hm*36; i += 256) ((float*)hs)[i] = 0.f;

    float cst[16];
#pragma unroll
    for (int r = 0; r < 16; r++) cst[r] = 0.f;
    __syncthreads();

    int cur = 0;
    const float* wp = whhT + j;

    for (int li = 0; li < Lm; li++) {
        int l = dir ? (Lm-1-li) : li;

        float acc[4][16];
#pragma unroll
        for (int g = 0; g < 4; g++)
#pragma unroll
            for (int r = 0; r < 16; r++)
                acc[g][r] = gates[((size_t)(r0 + half*16 + r)*Lm + l)*G4 + g*128 + j];

#pragma unroll 4
        for (int k = 0; k < Hm; k++) {
            float w0 = wp[k*G4 + 0];
            float w1 = wp[k*G4 + 128];
            float w2 = wp[k*G4 + 256];
            float w3 = wp[k*G4 + 384];
#pragma unroll
            for (int q = 0; q < 4; q++) {
                float4 h4 = *(const float4*)&hs[cur][k][half*16 + q*4];
                float hv[4] = {h4.x, h4.y, h4.z, h4.w};
#pragma unroll
                for (int e = 0; e < 4; e++) {
                    acc[0][q*4+e] += w0*hv[e];
                    acc[1][q*4+e] += w1*hv[e];
                    acc[2][q*4+e] += w2*hv[e];
                    acc[3][q*4+e] += w3*hv[e];
                }
            }
        }

#pragma unroll
        for (int r = 0; r < 16; r++) {
            float ig = 1.f/(1.f + expf(-acc[0][r]));
            float fg = 1.f/(1.f + expf(-acc[1][r]));
            float gg = tanhf(acc[2][r]);
            float og = 1.f/(1.f + expf(-acc[3][r]));
            float cn = fg*cst[r] + ig*gg;
            cst[r] = cn;
            float hn = og*tanhf(cn);
            hs[cur^1][j][half*16 + r] = hn;
            hout[((size_t)(r0 + half*16 + r)*Lm + l)*Hm + j] = hn;
        }
        cur ^= 1;
        __syncthreads();
    }
}

// ======================= emission (BN2+FC folded) =======================
__global__ void emission_kernel()
{
    int gt = blockIdx.x*blockDim.x + threadIdx.x;
    int warp = gt >> 5;
    int lane = threadIdx.x & 31;
    if (warp >= Nt) return;
    float4 hf4 = *(const float4*)&g_h[0][(size_t)warp*Hm + lane*4];
    float4 hb4 = *(const float4*)&g_h[1][(size_t)warp*Hm + lane*4];
#pragma unroll
    for (int tt = 0; tt < Tm; tt++) {
        float4 f4 = *(const float4*)&g_fcf[tt*Hm + lane*4];
        float4 b4 = *(const float4*)&g_fcb[tt*Hm + lane*4];
        float s = hf4.x*f4.x + hf4.y*f4.y + hf4.z*f4.z + hf4.w*f4.w
                + hb4.x*b4.x + hb4.y*b4.y + hb4.z*b4.z + hb4.w*b4.w;
#pragma unroll
        for (int o = 16; o; o >>= 1) s += __shfl_xor_sync(0xffffffffu, s, o);
        if (lane == 0) g_emis[(size_t)warp*Tm + tt] = s + g_cbias[tt];
    }
}

// ======================= Viterbi =======================
__global__ void viterbi_kernel(const int* __restrict__ x,
                               const float* __restrict__ trans,
                               const float* __restrict__ start_t,
                               const float* __restrict__ end_t,
                               float* __restrict__ out)
{
    int b = blockIdx.x*blockDim.x + threadIdx.x;
    if (b >= Bsz) return;
    float tr[9];
#pragma unroll
    for (int i = 0; i < 9; i++) tr[i] = trans[i];
    const float* em = g_emis + (size_t)b*Lm*Tm;
    float sc[3];
#pragma unroll
    for (int t = 0; t < 3; t++) sc[t] = start_t[t] + em[t];

    unsigned char hist[Lm-1][3];
    for (int l = 1; l < Lm; l++) {
        bool m = x[(b*Lm + l)*Wm + 2] > 0;
        float ns[3];
#pragma unroll
        for (int t = 0; t < 3; t++) {
            float best = sc[0] + tr[0*3 + t];
            int bp = 0;
#pragma unroll
            for (int p = 1; p < 3; p++) {
                float v = sc[p] + tr[p*3 + t];
                if (v > best) { best = v; bp = p; }
            }
            hist[l-1][t] = (unsigned char)bp;
            ns[t] = best + em[l*Tm + t];
        }
        if (m) { sc[0]=ns[0]; sc[1]=ns[1]; sc[2]=ns[2]; }
    }
#pragma unroll
    for (int t = 0; t < 3; t++) sc[t] += end_t[t];
    float best = sc[0]; int last = 0;
    if (sc[1] > best) { best = sc[1]; last = 1; }
    if (sc[2] > best) { best = sc[2]; last = 2; }
    out[b] = best;

    float* tagout = out + Bsz;
    int tag = last;
    tagout[(size_t)b*Lm + (Lm-1)] = (float)tag;
    for (int i = Lm-2; i >= 0; i--) {
        int prev = hist[i][tag];
        bool m = x[(b*Lm + i + 1)*Wm + 2] > 0;
        if (m) tag = prev;
        tagout[(size_t)b*Lm + i] = (float)tag;
    }
}

// ======================= launch =======================
extern "C" void kernel_launch(void* const* d_in, const int* in_sizes, int n_in,
                              void* d_out, int out_size)
{
    (void)in_sizes; (void)n_in; (void)out_size;
    const int*   x      = (const int*)  d_in[0];
    const float* emb    = (const float*)d_in[1];
    const float* conv_w = (const float*)d_in[2];
    const float* conv_b = (const float*)d_in[3];
    const float* bn1_g  = (const float*)d_in[4];
    const float* bn1_b  = (const float*)d_in[5];
    const float* bn1_m  = (const float*)d_in[6];
    const float* bn1_v  = (const float*)d_in[7];
    const float* w_ih_f = (const float*)d_in[8];
    const float* w_hh_f = (const float*)d_in[9];
    const float* b_f    = (const float*)d_in[10];
    const float* w_ih_b = (const float*)d_in[11];
    const float* w_hh_b = (const float*)d_in[12];
    const float* b_b    = (const float*)d_in[13];
    const float* bn2_g  = (const float*)d_in[14];
    const float* bn2_b  = (const float*)d_in[15];
    const float* bn2_m  = (const float*)d_in[16];
    const float* bn2_v  = (const float*)d_in[17];
    const float* fc_w   = (const float*)d_in[18];
    const float* fc_b   = (const float*)d_in[19];
    const float* trans  = (const float*)d_in[20];
    const float* start_t= (const float*)d_in[21];
    const float* end_t  = (const float*)d_in[22];
    float* out = (float*)d_out;

    prep_tables<<<(Am*Cch*3 + Cch + 255)/256, 256>>>(emb, conv_w, conv_b,
                                                     bn1_g, bn1_b, bn1_m, bn1_v);
    prep_pack<<<512, 256>>>(w_ih_f, w_hh_f, w_ih_b, w_hh_b);
    prep_fc<<<1, 256>>>(bn2_g, bn2_b, bn2_m, bn2_v, fc_w, fc_b);

    featurize<<<(Nt*Cch + 255)/256, 256>>>(x);

    dim3 gg(Nt/64, G4/64);
    gemm_gates<<<gg, 256>>>(0, b_f);
    gemm_gates<<<gg, 256>>>(1, b_b);

    lstm_kernel<<<Bsz/32, 256>>>(0);
    lstm_kernel<<<Bsz/32, 256>>>(1);

    emission_kernel<<<(Nt + 3)/4, 128>>>();

    viterbi_kernel<<<(Bsz + 127)/128, 128>>>(x, trans, start_t, end_t, out);
}

// round 2
// speedup vs baseline: 1.3790x; 1.3790x over previous
#include <cuda_runtime.h>
#include <math.h>

// ---- problem constants ----
#define Bsz 4096
#define Lm  30
#define Wm  5
#define Am  30
#define Em  128
#define Cch 40
#define Hm  128
#define Tm  3
#define LIN 200
#define FK  208          // padded K for GEMM
#define Nt  (Bsz*Lm)     // 122880 tokens
#define G4  512          // 4*H gates

typedef unsigned long long u64;

// ---- packed f32x2 helpers (FFMA2 path, sm_103a) ----
__device__ __forceinline__ u64 pack2(float lo, float hi) {
    u64 r; asm("mov.b64 %0,{%1,%2};" : "=l"(r) : "f"(lo), "f"(hi)); return r;
}
__device__ __forceinline__ u64 splat2(float v) { return pack2(v, v); }
__device__ __forceinline__ u64 fma2(u64 a, u64 b, u64 c) {
    u64 d; asm("fma.rn.f32x2 %0,%1,%2,%3;" : "=l"(d) : "l"(a), "l"(b), "l"(c)); return d;
}
__device__ __forceinline__ void unpack2(u64 v, float& lo, float& hi) {
    asm("mov.b64 {%0,%1},%2;" : "=f"(lo), "=f"(hi) : "l"(v));
}
__device__ __forceinline__ float sigf(float x) {
    return __fdividef(1.f, 1.f + __expf(-x));
}
__device__ __forceinline__ float tanhfast(float x) {
    return __fdividef(2.f, 1.f + __expf(-2.f * x)) - 1.f;
}

// ---- device scratch (static, allowed) ----
__device__ float g_M[Am*Cch*3];        // folded emb*conv*bn
__device__ float g_bias1[Cch];
__device__ float g_wihP[2][G4*FK];     // padded input weights [dir][g][k]
__device__ float g_whhT[2][Hm*G4];     // transposed recurrent weights [dir][k][g]
__device__ float g_fcf[Tm*Hm];
__device__ float g_fcb[Tm*Hm];
__device__ float g_cbias[Tm];
__device__ float g_feat[(size_t)Nt*FK];        // ~102 MB
__device__ float g_gates[2][(size_t)Nt*G4];    // ~503 MB
__device__ float g_h[2][(size_t)Nt*Hm];        // ~126 MB
__device__ float g_emis[(size_t)Nt*Tm];

// ======================= prep kernels =======================
__global__ void prep_tables(const float* __restrict__ emb,
                            const float* __restrict__ conv_w,
                            const float* __restrict__ conv_b,
                            const float* __restrict__ g1,
                            const float* __restrict__ b1,
                            const float* __restrict__ m1,
                            const float* __restrict__ v1)
{
    int i = blockIdx.x*blockDim.x + threadIdx.x;
    if (i < Am*Cch*3) {
        int k = i % 3;
        int c = (i/3) % Cch;
        int a = i / (3*Cch);
        float s = 0.f;
        for (int e = 0; e < Em; e++)
            s += emb[a*Em + e] * conv_w[(c*Em + e)*3 + k];
        float sc = g1[c] * rsqrtf(v1[c] + 1e-5f);
        g_M[i] = s * sc;
    } else if (i < Am*Cch*3 + Cch) {
        int c = i - Am*Cch*3;
        float sc = g1[c] * rsqrtf(v1[c] + 1e-5f);
        g_bias1[c] = (conv_b[c] - m1[c]) * sc + b1[c];
    }
}

__global__ void prep_pack(const float* __restrict__ wihf, const float* __restrict__ whhf,
                          const float* __restrict__ wihb, const float* __restrict__ whhb)
{
    int stride = gridDim.x * blockDim.x;
    int t0 = blockIdx.x*blockDim.x + threadIdx.x;
    for (int i = t0; i < G4*FK; i += stride) {
        int g = i / FK, k = i % FK;
        float vf = (k < LIN) ? wihf[g*LIN + k] : 0.f;
        float vb = (k < LIN) ? wihb[g*LIN + k] : 0.f;
        g_wihP[0][i] = vf;
        g_wihP[1][i] = vb;
    }
    for (int i = t0; i < Hm*G4; i += stride) {
        int k = i / G4, g = i % G4;
        g_whhT[0][i] = whhf[g*Hm + k];
        g_whhT[1][i] = whhb[g*Hm + k];
    }
}

__global__ void prep_fc(const float* __restrict__ g2, const float* __restrict__ b2,
                        const float* __restrict__ m2, const float* __restrict__ v2,
                        const float* __restrict__ fcw, const float* __restrict__ fcbias)
{
    int t = threadIdx.x;
    if (t < Hm) {
        float s2a = g2[t]       * rsqrtf(v2[t]       + 1e-5f);
        float s2b = g2[Hm + t]  * rsqrtf(v2[Hm + t]  + 1e-5f);
        for (int tt = 0; tt < Tm; tt++) {
            g_fcf[tt*Hm + t] = fcw[tt*2*Hm + t]      * s2a;
            g_fcb[tt*Hm + t] = fcw[tt*2*Hm + Hm + t] * s2b;
        }
    }
    if (t < Tm) {
        float s = fcbias[t];
        for (int j = 0; j < 2*Hm; j++) {
            float s2 = g2[j] * rsqrtf(v2[j] + 1e-5f);
            s += (b2[j] - m2[j]*s2) * fcw[t*2*Hm + j];
        }
        g_cbias[t] = s;
    }
}

// ======================= featurize (conv+bn+relu+pool) =======================
__global__ void featurize(const int* __restrict__ x)
{
    int idx = blockIdx.x*blockDim.x + threadIdx.x;
    if (idx >= Nt*Cch) return;
    int n = idx / Cch, c = idx % Cch;
    int sym[Wm];
#pragma unroll
    for (int w = 0; w < Wm; w++) sym[w] = x[n*Wm + w];
    float y[Wm];
    float bb = g_bias1[c];
#pragma unroll
    for (int w = 0; w < Wm; w++) {
        float v = bb;
#pragma unroll
        for (int k = 0; k < 3; k++) {
            int p = w + k - 1;
            if (p >= 0 && p < Wm)
                v += g_M[sym[p]*(Cch*3) + c*3 + k];
        }
        y[w] = fmaxf(v, 0.f);
    }
    size_t base = (size_t)n*FK + c*Wm;
#pragma unroll
    for (int w = 0; w < Wm; w++) {
        float p = y[w];
        if (w > 0)      p = fmaxf(p, y[w-1]);
        if (w < Wm-1)   p = fmaxf(p, y[w+1]);
        g_feat[base + w] = p;
    }
    if (c < FK - LIN) g_feat[(size_t)n*FK + LIN + c] = 0.f; // zero pad columns
}

// ======================= input GEMM (f32x2 packed) =======================
// block tile 128(M) x 64(N), 256 threads, per-thread 8x4 as f32x2 m-pairs.
// blockIdx.x = (dir<<3)|n_tile so all consumers of an A-panel run adjacently.
__global__ __launch_bounds__(256) void gemm_gates2(const float* __restrict__ bias_f,
                                                   const float* __restrict__ bias_b)
{
    int dir = blockIdx.x >> 3;
    int n0  = (blockIdx.x & 7) * 64;
    int m0  = blockIdx.y * 128;
    const float* __restrict__ A  = g_feat;
    const float* __restrict__ Bt = g_wihP[dir];
    float* __restrict__ Co = g_gates[dir];
    const float* __restrict__ bias = dir ? bias_b : bias_f;

    __shared__ __align__(16) float As[16][128];
    __shared__ __align__(16) float Bs[16][64];

    int t = threadIdx.x;
    int alr = t >> 1, alc = (t & 1) * 8;
    int blr = t & 63, blc = (t >> 6) * 4;
    int tn = t & 15, tm = t >> 4;

    u64 acc2[4][4];
#pragma unroll
    for (int i = 0; i < 4; i++)
#pragma unroll
        for (int j = 0; j < 4; j++) acc2[i][j] = 0ULL;

    for (int k0 = 0; k0 < FK; k0 += 16) {
        float4 a0 = *(const float4*)(A  + (size_t)(m0+alr)*FK + k0 + alc);
        float4 a1 = *(const float4*)(A  + (size_t)(m0+alr)*FK + k0 + alc + 4);
        float4 bv = *(const float4*)(Bt + (size_t)(n0+blr)*FK + k0 + blc);
        __syncthreads();
        As[alc+0][alr]=a0.x; As[alc+1][alr]=a0.y; As[alc+2][alr]=a0.z; As[alc+3][alr]=a0.w;
        As[alc+4][alr]=a1.x; As[alc+5][alr]=a1.y; As[alc+6][alr]=a1.z; As[alc+7][alr]=a1.w;
        Bs[blc+0][blr]=bv.x; Bs[blc+1][blr]=bv.y; Bs[blc+2][blr]=bv.z; Bs[blc+3][blr]=bv.w;
        __syncthreads();
#pragma unroll
        for (int k = 0; k < 16; k++) {
            const u64* ap = (const u64*)&As[k][tm*8];
            float4 b4 = *(const float4*)&Bs[k][tn*4];
            u64 bs0 = splat2(b4.x), bs1 = splat2(b4.y);
            u64 bs2 = splat2(b4.z), bs3 = splat2(b4.w);
            u64 am0 = ap[0], am1 = ap[1], am2 = ap[2], am3 = ap[3];
            acc2[0][0] = fma2(am0, bs0, acc2[0][0]);
            acc2[0][1] = fma2(am0, bs1, acc2[0][1]);
            acc2[0][2] = fma2(am0, bs2, acc2[0][2]);
            acc2[0][3] = fma2(am0, bs3, acc2[0][3]);
            acc2[1][0] = fma2(am1, bs0, acc2[1][0]);
            acc2[1][1] = fma2(am1, bs1, acc2[1][1]);
            acc2[1][2] = fma2(am1, bs2, acc2[1][2]);
            acc2[1][3] = fma2(am1, bs3, acc2[1][3]);
            acc2[2][0] = fma2(am2, bs0, acc2[2][0]);
            acc2[2][1] = fma2(am2, bs1, acc2[2][1]);
            acc2[2][2] = fma2(am2, bs2, acc2[2][2]);
            acc2[2][3] = fma2(am2, bs3, acc2[2][3]);
            acc2[3][0] = fma2(am3, bs0, acc2[3][0]);
            acc2[3][1] = fma2(am3, bs1, acc2[3][1]);
            acc2[3][2] = fma2(am3, bs2, acc2[3][2]);
            acc2[3][3] = fma2(am3, bs3, acc2[3][3]);
        }
    }
    int gcol = n0 + tn*4;
    float b0 = bias[gcol], b1 = bias[gcol+1], b2 = bias[gcol+2], b3 = bias[gcol+3];
#pragma unroll
    for (int mp = 0; mp < 4; mp++) {
        float lo0,hi0,lo1,hi1,lo2,hi2,lo3,hi3;
        unpack2(acc2[mp][0], lo0, hi0);
        unpack2(acc2[mp][1], lo1, hi1);
        unpack2(acc2[mp][2], lo2, hi2);
        unpack2(acc2[mp][3], lo3, hi3);
        size_t r = (size_t)(m0 + tm*8 + mp*2);
        float4 o0; o0.x = lo0+b0; o0.y = lo1+b1; o0.z = lo2+b2; o0.w = lo3+b3;
        float4 o1; o1.x = hi0+b0; o1.y = hi1+b1; o1.z = hi2+b2; o1.w = hi3+b3;
        *(float4*)(Co + r*G4 + gcol)     = o0;
        *(float4*)(Co + (r+1)*G4 + gcol) = o1;
    }
}

// ======================= LSTM recurrence (both dirs fused, f32x2) =======================
// grid 256: dir = blockIdx.x>>7. One block = 32 batch rows, 256 threads:
// j = t&127 (H index), half = t>>7 picks 16 rows. h in shared (k-major,
// double buffered), c in registers, accumulators packed as row-pair f32x2.
__global__ __launch_bounds__(256, 2) void lstm_fused()
{
    int dir = blockIdx.x >> 7;
    int blk = blockIdx.x & 127;
    const float* __restrict__ gates = g_gates[dir];
    const float* __restrict__ whhT  = g_whhT[dir];
    float* __restrict__ hout        = g_h[dir];

    __shared__ __align__(16) float hs[2][Hm][36];

    int t = threadIdx.x;
    int j = t & 127;
    int half = t >> 7;
    int r0 = blk * 32 + half * 16;

    for (int i = t; i < 2*Hm*36; i += 256) ((float*)hs)[i] = 0.f;

    float cst[16];
#pragma unroll
    for (int r = 0; r < 16; r++) cst[r] = 0.f;
    __syncthreads();

    int cur = 0;
    const float* wp = whhT + j;

    for (int li = 0; li < Lm; li++) {
        int l = dir ? (Lm-1-li) : li;

        u64 acc2[4][8];
#pragma unroll
        for (int g = 0; g < 4; g++)
#pragma unroll
            for (int q = 0; q < 8; q++) {
                size_t base = ((size_t)(r0 + 2*q)*Lm + l)*G4 + g*128 + j;
                float lo = gates[base];
                float hi = gates[base + (size_t)Lm*G4];
                acc2[g][q] = pack2(lo, hi);
            }

#pragma unroll 4
        for (int k = 0; k < Hm; k++) {
            float w0 = wp[k*G4 + 0];
            float w1 = wp[k*G4 + 128];
            float w2 = wp[k*G4 + 256];
            float w3 = wp[k*G4 + 384];
            u64 w0p = splat2(w0), w1p = splat2(w1);
            u64 w2p = splat2(w2), w3p = splat2(w3);
            const u64* hp = (const u64*)&hs[cur][k][half*16];
#pragma unroll
            for (int q = 0; q < 8; q++) {
                u64 hv = hp[q];
                acc2[0][q] = fma2(w0p, hv, acc2[0][q]);
                acc2[1][q] = fma2(w1p, hv, acc2[1][q]);
                acc2[2][q] = fma2(w2p, hv, acc2[2][q]);
                acc2[3][q] = fma2(w3p, hv, acc2[3][q]);
            }
        }

#pragma unroll
        for (int q = 0; q < 8; q++) {
            float zi0,zi1,zf0,zf1,zg0,zg1,zo0,zo1;
            unpack2(acc2[0][q], zi0, zi1);
            unpack2(acc2[1][q], zf0, zf1);
            unpack2(acc2[2][q], zg0, zg1);
            unpack2(acc2[3][q], zo0, zo1);
            {
                float ig = sigf(zi0), fg = sigf(zf0);
                float gg = tanhfast(zg0), og = sigf(zo0);
                float cn = fg*cst[2*q] + ig*gg;
                cst[2*q] = cn;
                float hn = og * tanhfast(cn);
                hs[cur^1][j][half*16 + 2*q] = hn;
                hout[((size_t)(r0 + 2*q)*Lm + l)*Hm + j] = hn;
            }
            {
                float ig = sigf(zi1), fg = sigf(zf1);
                float gg = tanhfast(zg1), og = sigf(zo1);
                float cn = fg*cst[2*q+1] + ig*gg;
                cst[2*q+1] = cn;
                float hn = og * tanhfast(cn);
                hs[cur^1][j][half*16 + 2*q + 1] = hn;
                hout[((size_t)(r0 + 2*q + 1)*Lm + l)*Hm + j] = hn;
            }
        }
        cur ^= 1;
        __syncthreads();
    }
}

// ======================= emission (BN2+FC folded) =======================
__global__ void emission_kernel()
{
    int gt = blockIdx.x*blockDim.x + threadIdx.x;
    int warp = gt >> 5;
    int lane = threadIdx.x & 31;
    if (warp >= Nt) return;
    float4 hf4 = *(const float4*)&g_h[0][(size_t)warp*Hm + lane*4];
    float4 hb4 = *(const float4*)&g_h[1][(size_t)warp*Hm + lane*4];
#pragma unroll
    for (int tt = 0; tt < Tm; tt++) {
        float4 f4 = *(const float4*)&g_fcf[tt*Hm + lane*4];
        float4 b4 = *(const float4*)&g_fcb[tt*Hm + lane*4];
        float s = hf4.x*f4.x + hf4.y*f4.y + hf4.z*f4.z + hf4.w*f4.w
                + hb4.x*b4.x + hb4.y*b4.y + hb4.z*b4.z + hb4.w*b4.w;
#pragma unroll
        for (int o = 16; o; o >>= 1) s += __shfl_xor_sync(0xffffffffu, s, o);
        if (lane == 0) g_emis[(size_t)warp*Tm + tt] = s + g_cbias[tt];
    }
}

// ======================= Viterbi =======================
__global__ void viterbi_kernel(const int* __restrict__ x,
                               const float* __restrict__ trans,
                               const float* __restrict__ start_t,
                               const float* __restrict__ end_t,
                               float* __restrict__ out)
{
    int b = blockIdx.x*blockDim.x + threadIdx.x;
    if (b >= Bsz) return;
    float tr[9];
#pragma unroll
    for (int i = 0; i < 9; i++) tr[i] = trans[i];
    const float* em = g_emis + (size_t)b*Lm*Tm;
    float sc[3];
#pragma unroll
    for (int t = 0; t < 3; t++) sc[t] = start_t[t] + em[t];

    unsigned char hist[Lm-1][3];
    for (int l = 1; l < Lm; l++) {
        bool m = x[(b*Lm + l)*Wm + 2] > 0;
        float ns[3];
#pragma unroll
        for (int t = 0; t < 3; t++) {
            float best = sc[0] + tr[0*3 + t];
            int bp = 0;
#pragma unroll
            for (int p = 1; p < 3; p++) {
                float v = sc[p] + tr[p*3 + t];
                if (v > best) { best = v; bp = p; }
            }
            hist[l-1][t] = (unsigned char)bp;
            ns[t] = best + em[l*Tm + t];
        }
        if (m) { sc[0]=ns[0]; sc[1]=ns[1]; sc[2]=ns[2]; }
    }
#pragma unroll
    for (int t = 0; t < 3; t++) sc[t] += end_t[t];
    float best = sc[0]; int last = 0;
    if (sc[1] > best) { best = sc[1]; last = 1; }
    if (sc[2] > best) { best = sc[2]; last = 2; }
    out[b] = best;

    float* tagout = out + Bsz;
    int tag = last;
    tagout[(size_t)b*Lm + (Lm-1)] = (float)tag;
    for (int i = Lm-2; i >= 0; i--) {
        int prev = hist[i][tag];
        bool m = x[(b*Lm + i + 1)*Wm + 2] > 0;
        if (m) tag = prev;
        tagout[(size_t)b*Lm + i] = (float)tag;
    }
}

// ======================= launch =======================
extern "C" void kernel_launch(void* const* d_in, const int* in_sizes, int n_in,
                              void* d_out, int out_size)
{
    (void)in_sizes; (void)n_in; (void)out_size;
    const int*   x      = (const int*)  d_in[0];
    const float* emb    = (const float*)d_in[1];
    const float* conv_w = (const float*)d_in[2];
    const float* conv_b = (const float*)d_in[3];
    const float* bn1_g  = (const float*)d_in[4];
    const float* bn1_b  = (const float*)d_in[5];
    const float* bn1_m  = (const float*)d_in[6];
    const float* bn1_v  = (const float*)d_in[7];
    const float* w_ih_f = (const float*)d_in[8];
    const float* w_hh_f = (const float*)d_in[9];
    const float* b_f    = (const float*)d_in[10];
    const float* w_ih_b = (const float*)d_in[11];
    const float* w_hh_b = (const float*)d_in[12];
    const float* b_b    = (const float*)d_in[13];
    const float* bn2_g  = (const float*)d_in[14];
    const float* bn2_b  = (const float*)d_in[15];
    const float* bn2_m  = (const float*)d_in[16];
    const float* bn2_v  = (const float*)d_in[17];
    const float* fc_w   = (const float*)d_in[18];
    const float* fc_b   = (const float*)d_in[19];
    const float* trans  = (const float*)d_in[20];
    const float* start_t= (const float*)d_in[21];
    const float* end_t  = (const float*)d_in[22];
    float* out = (float*)d_out;

    prep_tables<<<(Am*Cch*3 + Cch + 255)/256, 256>>>(emb, conv_w, conv_b,
                                                     bn1_g, bn1_b, bn1_m, bn1_v);
    prep_pack<<<512, 256>>>(w_ih_f, w_hh_f, w_ih_b, w_hh_b);
    prep_fc<<<1, 256>>>(bn2_g, bn2_b, bn2_m, bn2_v, fc_w, fc_b);

    featurize<<<(Nt*Cch + 255)/256, 256>>>(x);

    dim3 gg(16, Nt/128);
    gemm_gates2<<<gg, 256>>>(b_f, b_b);

    lstm_fused<<<256, 256>>>();

    emission_kernel<<<(Nt + 3)/4, 128>>>();

    viterbi_kernel<<<(Bsz + 127)/128, 128>>>(x, trans, start_t, end_t, out);
}